// round 13
// baseline (speedup 1.0000x reference)
#include <cuda_runtime.h>
#include <cuda_bf16.h>
#include <cuda_fp16.h>
#include <cstdint>
#include <math.h>

#define B_SZ  2
#define S_LEN 2048
#define HID   1024
#define NH    16
#define HD    64
#define M_TOK (B_SZ * S_LEN)     // 4096

#define LOG2E 1.44269504088896341f

// ---------------------------------------------------------------------------
// Scratch (__device__ globals per allocation-free rule) — all single f16
// ---------------------------------------------------------------------------
__device__ __half g_A[(size_t)M_TOK * HID];          // activations (input / ctx)
__device__ __half g_B[(size_t)3 * HID * HID];        // weights [N][K]
#define HELEMS ((size_t)B_SZ * NH * S_LEN * HD)
__device__ __half g_Q[HELEMS];                       // Q (scaled by 0.125*log2e)
__device__ __half g_K[HELEMS];
__device__ __half g_V[HELEMS];

// ---------------------------------------------------------------------------
// PTX helpers (family-compatible: mma.sync / ldmatrix / cp.async only)
// ---------------------------------------------------------------------------
__device__ __forceinline__ uint32_t smem_u32(const void* p) {
    uint32_t a;
    asm("{ .reg .u64 t; cvta.to.shared.u64 t, %1; cvt.u32.u64 %0, t; }"
        : "=r"(a) : "l"(p));
    return a;
}

#define CP_ASYNC16(dst, src) \
    asm volatile("cp.async.cg.shared.global [%0], [%1], 16;" \
                 :: "r"(dst), "l"(src) : "memory")
#define CP_COMMIT() asm volatile("cp.async.commit_group;" ::: "memory")
#define CP_WAIT1()  asm volatile("cp.async.wait_group 1;" ::: "memory")
#define CP_WAIT0()  asm volatile("cp.async.wait_group 0;" ::: "memory")

#define LDSM_X4(r0, r1, r2, r3, addr) \
    asm volatile("ldmatrix.sync.aligned.m8n8.x4.shared.b16 {%0,%1,%2,%3}, [%4];" \
                 : "=r"(r0), "=r"(r1), "=r"(r2), "=r"(r3) : "r"(addr))
#define LDSM_X4_T(r0, r1, r2, r3, addr) \
    asm volatile("ldmatrix.sync.aligned.m8n8.x4.trans.shared.b16 {%0,%1,%2,%3}, [%4];" \
                 : "=r"(r0), "=r"(r1), "=r"(r2), "=r"(r3) : "r"(addr))

__device__ __forceinline__ void mma_f16(float* c, const uint32_t* a,
                                        uint32_t b0, uint32_t b1) {
    asm volatile(
        "mma.sync.aligned.m16n8k16.row.col.f32.f16.f16.f32 "
        "{%0,%1,%2,%3}, {%4,%5,%6,%7}, {%8,%9}, {%0,%1,%2,%3};"
        : "+f"(c[0]), "+f"(c[1]), "+f"(c[2]), "+f"(c[3])
        : "r"(a[0]), "r"(a[1]), "r"(a[2]), "r"(a[3]), "r"(b0), "r"(b1));
}

__device__ __forceinline__ uint32_t pack_h2(float a, float b) {
    __half2 h = __floats2half2_rn(a, b);
    return *reinterpret_cast<uint32_t*>(&h);
}

// ---------------------------------------------------------------------------
// Prep kernels
// ---------------------------------------------------------------------------
__global__ void convert_f16(const float* __restrict__ x,
                            __half* __restrict__ y, int n4) {
    int i = blockIdx.x * blockDim.x + threadIdx.x;
    if (i >= n4) return;
    float4 v = ((const float4*)x)[i];
    uint32_t* yp = (uint32_t*)(y + (size_t)i * 4);
    yp[0] = pack_h2(v.x, v.y);
    yp[1] = pack_h2(v.z, v.w);
}

// W [K,N] fp32 row-major  ->  Wt [N,K] f16 row-major (K-major for MMA)
__global__ void transpose_f16(const float* __restrict__ W,
                              __half* __restrict__ T, int K, int N) {
    __shared__ float t[32][33];
    int tx = threadIdx.x, ty = threadIdx.y;
    int n0 = blockIdx.x * 32, k0 = blockIdx.y * 32;
#pragma unroll
    for (int j = 0; j < 4; j++) {
        int k = k0 + ty + j * 8;
        t[ty + j * 8][tx] = W[(size_t)k * N + n0 + tx];
    }
    __syncthreads();
#pragma unroll
    for (int j = 0; j < 4; j++) {
        int n = n0 + ty + j * 8;
        T[(size_t)n * K + k0 + tx] = __float2half_rn(t[tx][ty + j * 8]);
    }
}

// ---------------------------------------------------------------------------
// mma.sync single-f16 GEMM (R10 config: 128x128 tile, 256 thr, 2 CTAs/SM),
// K-chunk 64, 3-stage cp.async.
// MODE 0: C = A@Wt^T + bias (fp32 out)
// MODE 1: QKV epilogue -> Q (scaled), K, V single f16 per-head
// ---------------------------------------------------------------------------
#define CH_K   64
#define LDT_B  144                       // 64 halfs (128B) + 16B pad
#define TILE_B (128 * LDT_B)             // 18432 B
#define STAGE_B (2 * TILE_B)             // A + B = 36864 B
#define GEMM_SMEM (3 * STAGE_B)          // 110592 B -> 2 CTAs/SM

__device__ __forceinline__ void issue_tile(const __half* __restrict__ g,
                                           int row0, int K, int kt,
                                           uint32_t smem, int tid) {
#pragma unroll
    for (int i = 0; i < 4; i++) {
        int v = tid + i * 256;           // 128 rows x 8 16B-chunks
        int r = v >> 3, c = v & 7;
        CP_ASYNC16(smem + (uint32_t)(r * LDT_B + c * 16),
                   g + (size_t)(row0 + r) * K + kt + c * 8);
    }
}

template<int MODE>
__global__ __launch_bounds__(256, 2) void gemm_tc(
    const __half* __restrict__ A, const __half* __restrict__ B,
    const float* __restrict__ bias, float* __restrict__ C,
    __half* __restrict__ Q, __half* __restrict__ Kd, __half* __restrict__ V,
    int M, int N, int K)
{
    extern __shared__ char sm[];
    uint32_t sb = smem_u32(sm);
    const int tid  = threadIdx.x;
    const int lane = tid & 31;
    const int wid  = tid >> 5;
    const int m0   = (wid & 3) * 32;
    const int n0   = (wid >> 2) * 64;
    const int bm   = blockIdx.y * 128;
    const int bn   = blockIdx.x * 128;

    float acc[2][8][4];
#pragma unroll
    for (int i = 0; i < 2; i++)
#pragma unroll
        for (int j = 0; j < 8; j++)
#pragma unroll
            for (int q = 0; q < 4; q++) acc[i][j][q] = 0.f;

    const uint32_t a_row  = lane & 15;
    const uint32_t a_koff = ((lane >> 4) & 1) * 16;
    const uint32_t b_rin  = ((lane >> 4) & 1) * 8 + (lane & 7);
    const uint32_t b_koff = ((lane >> 3) & 1) * 16;

    const int NCH = K / CH_K;

    // prologue: stage chunks 0, 1 into slots 0, 1
#pragma unroll
    for (int p = 0; p < 2; p++) {
        uint32_t bb = sb + p * STAGE_B;
        issue_tile(A, bm, K, p * CH_K, bb + 0 * TILE_B, tid);
        issue_tile(B, bn, K, p * CH_K, bb + 1 * TILE_B, tid);
        CP_COMMIT();
    }

    for (int c = 0; c < NCH; c++) {
        if (c + 1 < NCH) { CP_WAIT1(); } else { CP_WAIT0(); }
        __syncthreads();   // chunk c visible; slot (c+2)%3 free (read at c-1)

        if (c + 2 < NCH) {
            uint32_t nb = sb + (uint32_t)((c + 2) % 3) * STAGE_B;
            int kt = (c + 2) * CH_K;
            issue_tile(A, bm, K, kt, nb + 0 * TILE_B, tid);
            issue_tile(B, bn, K, kt, nb + 1 * TILE_B, tid);
            CP_COMMIT();
        }

        uint32_t bb  = sb + (uint32_t)(c % 3) * STAGE_B;
        uint32_t A_s = bb + 0 * TILE_B;
        uint32_t B_s = bb + 1 * TILE_B;

#pragma unroll
        for (int kk = 0; kk < 4; kk++) {
            uint32_t af[2][4];
#pragma unroll
            for (int i = 0; i < 2; i++) {
                uint32_t ro = (uint32_t)(m0 + i * 16 + a_row) * LDT_B
                              + kk * 32 + a_koff;
                LDSM_X4(af[i][0], af[i][1], af[i][2], af[i][3], A_s + ro);
            }
#pragma unroll
            for (int jp = 0; jp < 4; jp++) {
                uint32_t ro = (uint32_t)(n0 + jp * 16 + b_rin) * LDT_B
                              + kk * 32 + b_koff;
                uint32_t b0, b1, b2, b3;
                LDSM_X4(b0, b1, b2, b3, B_s + ro);
                mma_f16(acc[0][jp * 2 + 0], af[0], b0, b1);
                mma_f16(acc[0][jp * 2 + 1], af[0], b2, b3);
                mma_f16(acc[1][jp * 2 + 0], af[1], b0, b1);
                mma_f16(acc[1][jp * 2 + 1], af[1], b2, b3);
            }
        }
    }

    const int rrow = lane >> 2;
    const int rcol = (lane & 3) * 2;
#pragma unroll
    for (int i = 0; i < 2; i++) {
        int r_lo = bm + m0 + i * 16 + rrow;
#pragma unroll
        for (int half = 0; half < 2; half++) {
            int row = r_lo + half * 8;
#pragma unroll
            for (int j = 0; j < 8; j++) {
                int col = bn + n0 + j * 8 + rcol;
                float b0 = bias[col], b1 = bias[col + 1];
                float v0 = acc[i][j][half * 2 + 0] + b0;
                float v1 = acc[i][j][half * 2 + 1] + b1;
                if (MODE == 0) {
                    *(float2*)&C[(size_t)row * N + col] = make_float2(v0, v1);
                } else {
                    int sec = col >> 10;           // 0=q 1=k 2=v
                    int hh  = (col & 1023) >> 6;
                    int d   = col & 63;
                    int b   = row >> 11, s = row & 2047;
                    size_t dst = (((size_t)(b * NH + hh)) * S_LEN + s) * HD + d;
                    if (sec == 0) {                // Q: scale + base-2 fold
                        v0 *= 0.125f * LOG2E;
                        v1 *= 0.125f * LOG2E;
                    }
                    __half* p = (sec == 0) ? Q : (sec == 1) ? Kd : V;
                    *(uint32_t*)(p + dst) = pack_h2(v0, v1);
                }
            }
        }
    }
}

// ---------------------------------------------------------------------------
// Tensor-core flash attention (causal), all-f16 operands.
// 128-key staged blocks (one wait/sync per 128 keys), processed as two
// 64-column halves whose instruction sequence matches the previous per-64
// iterations exactly -> bit-identical numerics, half the barrier overhead.
// ---------------------------------------------------------------------------
#define ALD       144
#define KV_TILE   (128 * ALD)        // 18432 B (128 keys x 144 B)
#define FA_STAGE  (2 * KV_TILE)      // K, V = 36864 B
#define FA_SMEM   (3 * FA_STAGE)     // 110592 B -> 2 CTAs/SM

__global__ __launch_bounds__(256, 2) void flash_tc(
    const __half* __restrict__ Q,
    const __half* __restrict__ K,
    const __half* __restrict__ V,
    __half* __restrict__ Cc)
{
    extern __shared__ char sm[];
    uint32_t sb = smem_u32(sm);
    const int tid = threadIdx.x, lane = tid & 31, wid = tid >> 5;
    const int qb = (int)gridDim.x - 1 - (int)blockIdx.x;   // big tiles first
    const int h = blockIdx.y, b = blockIdx.z;
    const size_t hoff = ((size_t)(b * NH + h)) * S_LEN * HD;
    const __half* Q_g = Q + hoff + (size_t)qb * 128 * HD;
    const __half* K_g = K + hoff;
    const __half* V_g = V + hoff;

    // ---- stage Q (temporarily at sb), load fragments ----
#pragma unroll
    for (int i = 0; i < 4; i++) {
        int idx = tid + i * 256;
        int r = idx >> 3, c = idx & 7;
        CP_ASYNC16(sb + (uint32_t)(r * ALD + c * 16), Q_g + r * HD + c * 8);
    }
    CP_COMMIT(); CP_WAIT0(); __syncthreads();

    uint32_t qf[4][4];
    {
        uint32_t base = sb + (uint32_t)((wid * 16 + (lane & 15)) * ALD)
                        + ((lane >> 4) & 1) * 16;
#pragma unroll
        for (int ks = 0; ks < 4; ks++)
            LDSM_X4(qf[ks][0], qf[ks][1], qf[ks][2], qf[ks][3], base + ks * 32);
    }
    __syncthreads();

    float o[8][4];
#pragma unroll
    for (int j = 0; j < 8; j++)
#pragma unroll
        for (int q = 0; q < 4; q++) o[j][q] = 0.f;
    float m[2] = {-1e30f, -1e30f}, lpart[2] = {0.f, 0.f};

    const uint32_t b_rin  = ((lane >> 4) & 1) * 8 + (lane & 7);
    const uint32_t b_koff = ((lane >> 3) & 1) * 16;
    const uint32_t v_row  = (lane & 7) + ((lane >> 3) & 1) * 8;
    const uint32_t v_coff = ((lane >> 4) & 1) * 16;

    const int nIter = qb + 1;            // 128-key blocks

    // prologue: stage key-blocks 0, 1 into slots 0, 1
#pragma unroll
    for (int p = 0; p < 2; p++) {
        if (p < nIter) {
            uint32_t nb = sb + (uint32_t)p * FA_STAGE;
            int kbase = p * 128 * HD;
#pragma unroll
            for (int i = 0; i < 4; i++) {
                int idx = tid + i * 256;     // 128 rows x 8 chunks
                int r = idx >> 3, c = idx & 7;
                uint32_t d = nb + (uint32_t)(r * ALD + c * 16);
                int go = kbase + r * HD + c * 8;
                CP_ASYNC16(d + 0 * KV_TILE, K_g + go);
                CP_ASYNC16(d + 1 * KV_TILE, V_g + go);
            }
            CP_COMMIT();
        }
    }

    for (int it = 0; it < nIter; it++) {
        if (it + 1 < nIter) { CP_WAIT1(); } else { CP_WAIT0(); }
        __syncthreads();

        if (it + 2 < nIter) {
            uint32_t nb = sb + (uint32_t)((it + 2) % 3) * FA_STAGE;
            int kbase = (it + 2) * 128 * HD;
#pragma unroll
            for (int i = 0; i < 4; i++) {
                int idx = tid + i * 256;
                int r = idx >> 3, c = idx & 7;
                uint32_t d = nb + (uint32_t)(r * ALD + c * 16);
                int go = kbase + r * HD + c * 8;
                CP_ASYNC16(d + 0 * KV_TILE, K_g + go);
                CP_ASYNC16(d + 1 * KV_TILE, V_g + go);
            }
            CP_COMMIT();
        }

        uint32_t bb = sb + (uint32_t)(it % 3) * FA_STAGE;
        const bool diag = (it == qb);

#pragma unroll
        for (int half = 0; half < 2; half++) {
            uint32_t kb = bb + (uint32_t)half * (64 * ALD);

            // ---- S = Q K^T (single f16) ----
            float s[8][4];
#pragma unroll
            for (int j = 0; j < 8; j++)
#pragma unroll
                for (int q = 0; q < 4; q++) s[j][q] = 0.f;

#pragma unroll
            for (int ks = 0; ks < 4; ks++) {
#pragma unroll
                for (int jp = 0; jp < 4; jp++) {
                    uint32_t ka = kb + (uint32_t)((jp * 16 + b_rin) * ALD)
                                  + ks * 32 + b_koff;
                    uint32_t k0, k1, k2, k3;
                    LDSM_X4(k0, k1, k2, k3, ka);
                    mma_f16(s[jp * 2 + 0], qf[ks], k0, k1);
                    mma_f16(s[jp * 2 + 1], qf[ks], k2, k3);
                }
            }

            // ---- causal mask (diagonal block only) ----
            if (diag) {
                int col0 = it * 128 + half * 64 + (lane & 3) * 2;
#pragma unroll
                for (int rr = 0; rr < 2; rr++) {
                    int row = qb * 128 + wid * 16 + (lane >> 2) + rr * 8;
#pragma unroll
                    for (int j = 0; j < 8; j++) {
                        int c0 = col0 + j * 8;
                        if (c0 > row)     s[j][rr * 2 + 0] = -1e30f;
                        if (c0 + 1 > row) s[j][rr * 2 + 1] = -1e30f;
                    }
                }
            }

            // ---- deferred-base check + rare rescale ----
#pragma unroll
            for (int rr = 0; rr < 2; rr++) {
                float lmt = -1e30f;
#pragma unroll
                for (int j = 0; j < 8; j++)
                    lmt = fmaxf(lmt, fmaxf(s[j][rr * 2], s[j][rr * 2 + 1]));
                if (__any_sync(0xffffffffu, lmt > m[rr] + 8.0f)) {  // rare
                    float lm = fmaxf(lmt, __shfl_xor_sync(0xffffffffu, lmt, 1));
                    lm = fmaxf(lm, __shfl_xor_sync(0xffffffffu, lm, 2));
                    float mn = fmaxf(m[rr], lm);
                    float corr = exp2f(m[rr] - mn);
                    lpart[rr] *= corr;
#pragma unroll
                    for (int j = 0; j < 8; j++) {
                        o[j][rr * 2 + 0] *= corr;
                        o[j][rr * 2 + 1] *= corr;
                    }
                    m[rr] = mn;
                }
            }
            const float mn0 = m[0], mn1 = m[1];

            // ---- fused exp + pack + PV per ks-stage ----
            float sum0 = 0.f, sum1 = 0.f;
#pragma unroll
            for (int ks = 0; ks < 4; ks++) {
#pragma unroll
                for (int jj = 0; jj < 2; jj++) {
                    int j = 2 * ks + jj;
                    s[j][0] = exp2f(s[j][0] - mn0);
                    s[j][1] = exp2f(s[j][1] - mn0);
                    sum0 += s[j][0] + s[j][1];
                    s[j][2] = exp2f(s[j][2] - mn1);
                    s[j][3] = exp2f(s[j][3] - mn1);
                    sum1 += s[j][2] + s[j][3];
                }
                uint32_t p16[4];
                p16[0] = pack_h2(s[2 * ks][0],     s[2 * ks][1]);
                p16[1] = pack_h2(s[2 * ks][2],     s[2 * ks][3]);
                p16[2] = pack_h2(s[2 * ks + 1][0], s[2 * ks + 1][1]);
                p16[3] = pack_h2(s[2 * ks + 1][2], s[2 * ks + 1][3]);
                uint32_t va = bb + KV_TILE
                              + (uint32_t)((half * 64 + ks * 16 + v_row) * ALD)
                              + v_coff;
#pragma unroll
                for (int ng = 0; ng < 4; ng++) {
                    uint32_t v0, v1, v2, v3;
                    LDSM_X4_T(v0, v1, v2, v3, va + ng * 32);
                    mma_f16(o[ng * 2 + 0], p16, v0, v1);
                    mma_f16(o[ng * 2 + 1], p16, v2, v3);
                }
            }
            lpart[0] += sum0;
            lpart[1] += sum1;
        }
    }

    // ---- epilogue: quad-reduce l, O/l -> ctx f16 [tok][H] ----
#pragma unroll
    for (int rr = 0; rr < 2; rr++) {
        float lsum = lpart[rr];
        lsum += __shfl_xor_sync(0xffffffffu, lsum, 1);
        lsum += __shfl_xor_sync(0xffffffffu, lsum, 2);
        float inv = 1.0f / lsum;
        int tok = b * S_LEN + qb * 128 + wid * 16 + (lane >> 2) + rr * 8;
#pragma unroll
        for (int j = 0; j < 8; j++) {
            int col = h * HD + j * 8 + (lane & 3) * 2;
            *(uint32_t*)(Cc + (size_t)tok * HID + col) =
                pack_h2(o[j][rr * 2 + 0] * inv, o[j][rr * 2 + 1] * inv);
        }
    }
}

// ---------------------------------------------------------------------------
extern "C" void kernel_launch(void* const* d_in, const int* in_sizes, int n_in,
                              void* d_out, int out_size)
{
    (void)in_sizes; (void)n_in; (void)out_size;
    const float* hidden  = (const float*)d_in[0];
    // d_in[1] = ltor_mask: exactly causal lower-triangular; handled analytically
    const float* W_qkv   = (const float*)d_in[2];
    const float* b_qkv   = (const float*)d_in[3];
    const float* W_dense = (const float*)d_in[4];
    const float* b_dense = (const float*)d_in[5];
    float* out = (float*)d_out;

    __half *a, *bw, *qp, *kp, *vp;
    cudaGetSymbolAddress((void**)&a,  g_A);
    cudaGetSymbolAddress((void**)&bw, g_B);
    cudaGetSymbolAddress((void**)&qp, g_Q);
    cudaGetSymbolAddress((void**)&kp, g_K);
    cudaGetSymbolAddress((void**)&vp, g_V);

    cudaFuncSetAttribute(gemm_tc<0>,
                         cudaFuncAttributeMaxDynamicSharedMemorySize, GEMM_SMEM);
    cudaFuncSetAttribute(gemm_tc<1>,
                         cudaFuncAttributeMaxDynamicSharedMemorySize, GEMM_SMEM);
    cudaFuncSetAttribute(flash_tc,
                         cudaFuncAttributeMaxDynamicSharedMemorySize, FA_SMEM);

    // 1) convert hidden -> f16
    {
        int n4 = M_TOK * HID / 4;
        convert_f16<<<(n4 + 255) / 256, 256>>>(hidden, a, n4);
    }
    // 2) transpose W_qkv -> f16 [N][K]
    {
        dim3 grid(3 * HID / 32, HID / 32);
        transpose_f16<<<grid, dim3(32, 8)>>>(W_qkv, bw, HID, 3 * HID);
    }
    // 3) QKV GEMM with fused per-head epilogue (Q scaled 0.125*log2e)
    {
        dim3 grid(3 * HID / 128, M_TOK / 128);
        gemm_tc<1><<<grid, 256, GEMM_SMEM>>>(a, bw, b_qkv, nullptr,
                                             qp, kp, vp, M_TOK, 3 * HID, HID);
    }
    // 4) flash attention -> ctx f16 (into g_A, dense-GEMM input)
    {
        dim3 grid(S_LEN / 128, NH, B_SZ);
        flash_tc<<<grid, 256, FA_SMEM>>>(qp, kp, vp, a);
    }
    // 5) transpose W_dense -> f16
    {
        dim3 grid(HID / 32, HID / 32);
        transpose_f16<<<grid, dim3(32, 8)>>>(W_dense, bw, HID, HID);
    }
    // 6) dense GEMM -> out (fp32)
    {
        dim3 grid(HID / 128, M_TOK / 128);
        gemm_tc<0><<<grid, 256, GEMM_SMEM>>>(a, bw, b_dense, out,
                                             nullptr, nullptr, nullptr,
                                             M_TOK, HID, HID);
    }
}

// round 14
// speedup vs baseline: 1.0660x; 1.0660x over previous
#include <cuda_runtime.h>
#include <cuda_bf16.h>
#include <cuda_fp16.h>
#include <cstdint>
#include <math.h>

#define B_SZ  2
#define S_LEN 2048
#define HID   1024
#define NH    16
#define HD    64
#define M_TOK (B_SZ * S_LEN)     // 4096

#define LOG2E 1.44269504088896341f

// ---------------------------------------------------------------------------
// Scratch (__device__ globals per allocation-free rule) — all single f16
// ---------------------------------------------------------------------------
__device__ __half g_A[(size_t)M_TOK * HID];          // activations (input / ctx)
__device__ __half g_B[(size_t)3 * HID * HID];        // W_qkv^T [N][K]
__device__ __half g_B2[(size_t)HID * HID];           // W_dense^T [N][K]
#define HELEMS ((size_t)B_SZ * NH * S_LEN * HD)
__device__ __half g_Q[HELEMS];                       // Q (scaled by 0.125*log2e)
__device__ __half g_K[HELEMS];
__device__ __half g_V[HELEMS];

// ---------------------------------------------------------------------------
// PTX helpers (family-compatible: mma.sync / ldmatrix / cp.async only)
// ---------------------------------------------------------------------------
__device__ __forceinline__ uint32_t smem_u32(const void* p) {
    uint32_t a;
    asm("{ .reg .u64 t; cvta.to.shared.u64 t, %1; cvt.u32.u64 %0, t; }"
        : "=r"(a) : "l"(p));
    return a;
}

#define CP_ASYNC16(dst, src) \
    asm volatile("cp.async.cg.shared.global [%0], [%1], 16;" \
                 :: "r"(dst), "l"(src) : "memory")
#define CP_COMMIT() asm volatile("cp.async.commit_group;" ::: "memory")
#define CP_WAIT1()  asm volatile("cp.async.wait_group 1;" ::: "memory")
#define CP_WAIT0()  asm volatile("cp.async.wait_group 0;" ::: "memory")

#define LDSM_X4(r0, r1, r2, r3, addr) \
    asm volatile("ldmatrix.sync.aligned.m8n8.x4.shared.b16 {%0,%1,%2,%3}, [%4];" \
                 : "=r"(r0), "=r"(r1), "=r"(r2), "=r"(r3) : "r"(addr))
#define LDSM_X4_T(r0, r1, r2, r3, addr) \
    asm volatile("ldmatrix.sync.aligned.m8n8.x4.trans.shared.b16 {%0,%1,%2,%3}, [%4];" \
                 : "=r"(r0), "=r"(r1), "=r"(r2), "=r"(r3) : "r"(addr))

__device__ __forceinline__ void mma_f16(float* c, const uint32_t* a,
                                        uint32_t b0, uint32_t b1) {
    asm volatile(
        "mma.sync.aligned.m16n8k16.row.col.f32.f16.f16.f32 "
        "{%0,%1,%2,%3}, {%4,%5,%6,%7}, {%8,%9}, {%0,%1,%2,%3};"
        : "+f"(c[0]), "+f"(c[1]), "+f"(c[2]), "+f"(c[3])
        : "r"(a[0]), "r"(a[1]), "r"(a[2]), "r"(a[3]), "r"(b0), "r"(b1));
}

__device__ __forceinline__ uint32_t pack_h2(float a, float b) {
    __half2 h = __floats2half2_rn(a, b);
    return *reinterpret_cast<uint32_t*>(&h);
}

// ---------------------------------------------------------------------------
// Fused prep kernel: one launch does
//   blocks [0, NCVT)              : hidden fp32 -> f16
//   blocks [NCVT, NCVT+NTQ)       : W_qkv  [K,N] -> g_B  [N][K] f16
//   blocks [NCVT+NTQ, +NTD)       : W_dense[K,N] -> g_B2 [N][K] f16
// All partitions use 256 threads.
// ---------------------------------------------------------------------------
#define NCVT (M_TOK * HID / 4 / 256)         // 4096 blocks
#define NTQ  ((3 * HID / 32) * (HID / 32))   // 96*32 = 3072
#define NTD  ((HID / 32) * (HID / 32))       // 32*32 = 1024

__device__ __forceinline__ void transpose_body(const float* __restrict__ W,
                                               __half* __restrict__ T,
                                               int K, int N, int bx, int by,
                                               int tid, float* t /*[32][33]*/) {
    int tx = tid & 31, ty = tid >> 5;
    int n0 = bx * 32, k0 = by * 32;
#pragma unroll
    for (int j = 0; j < 4; j++) {
        int k = k0 + ty + j * 8;
        t[(ty + j * 8) * 33 + tx] = W[(size_t)k * N + n0 + tx];
    }
    __syncthreads();
#pragma unroll
    for (int j = 0; j < 4; j++) {
        int n = n0 + ty + j * 8;
        T[(size_t)n * K + k0 + tx] = __float2half_rn(t[tx * 33 + ty + j * 8]);
    }
}

__global__ __launch_bounds__(256) void prep_all(
    const float* __restrict__ hidden, __half* __restrict__ A,
    const float* __restrict__ W_qkv, __half* __restrict__ Bq,
    const float* __restrict__ W_dense, __half* __restrict__ Bd)
{
    __shared__ float t[32 * 33];
    int bid = blockIdx.x, tid = threadIdx.x;
    if (bid < NCVT) {
        int i = bid * 256 + tid;
        float4 v = ((const float4*)hidden)[i];
        uint32_t* yp = (uint32_t*)(A + (size_t)i * 4);
        yp[0] = pack_h2(v.x, v.y);
        yp[1] = pack_h2(v.z, v.w);
    } else if (bid < NCVT + NTQ) {
        int b = bid - NCVT;
        transpose_body(W_qkv, Bq, HID, 3 * HID,
                       b % (3 * HID / 32), b / (3 * HID / 32), tid, t);
    } else {
        int b = bid - NCVT - NTQ;
        transpose_body(W_dense, Bd, HID, HID,
                       b % (HID / 32), b / (HID / 32), tid, t);
    }
}

// ---------------------------------------------------------------------------
// mma.sync single-f16 GEMM (128x128 tile, 256 thr, 2 CTAs/SM),
// K-chunk 64, 3-stage cp.async.
// MODE 0: C = A@Wt^T + bias (fp32 out)
// MODE 1: QKV epilogue -> Q (scaled), K, V single f16 per-head
// ---------------------------------------------------------------------------
#define CH_K   64
#define LDT_B  144                       // 64 halfs (128B) + 16B pad
#define TILE_B (128 * LDT_B)             // 18432 B
#define STAGE_B (2 * TILE_B)             // A + B = 36864 B
#define GEMM_SMEM (3 * STAGE_B)          // 110592 B -> 2 CTAs/SM

__device__ __forceinline__ void issue_tile(const __half* __restrict__ g,
                                           int row0, int K, int kt,
                                           uint32_t smem, int tid) {
#pragma unroll
    for (int i = 0; i < 4; i++) {
        int v = tid + i * 256;           // 128 rows x 8 16B-chunks
        int r = v >> 3, c = v & 7;
        CP_ASYNC16(smem + (uint32_t)(r * LDT_B + c * 16),
                   g + (size_t)(row0 + r) * K + kt + c * 8);
    }
}

template<int MODE>
__global__ __launch_bounds__(256, 2) void gemm_tc(
    const __half* __restrict__ A, const __half* __restrict__ B,
    const float* __restrict__ bias, float* __restrict__ C,
    __half* __restrict__ Q, __half* __restrict__ Kd, __half* __restrict__ V,
    int M, int N, int K)
{
    extern __shared__ char sm[];
    uint32_t sb = smem_u32(sm);
    const int tid  = threadIdx.x;
    const int lane = tid & 31;
    const int wid  = tid >> 5;
    const int m0   = (wid & 3) * 32;
    const int n0   = (wid >> 2) * 64;
    const int bm   = blockIdx.y * 128;
    const int bn   = blockIdx.x * 128;

    float acc[2][8][4];
#pragma unroll
    for (int i = 0; i < 2; i++)
#pragma unroll
        for (int j = 0; j < 8; j++)
#pragma unroll
            for (int q = 0; q < 4; q++) acc[i][j][q] = 0.f;

    const uint32_t a_row  = lane & 15;
    const uint32_t a_koff = ((lane >> 4) & 1) * 16;
    const uint32_t b_rin  = ((lane >> 4) & 1) * 8 + (lane & 7);
    const uint32_t b_koff = ((lane >> 3) & 1) * 16;

    const int NCH = K / CH_K;

    // prologue: stage chunks 0, 1 into slots 0, 1
#pragma unroll
    for (int p = 0; p < 2; p++) {
        uint32_t bb = sb + p * STAGE_B;
        issue_tile(A, bm, K, p * CH_K, bb + 0 * TILE_B, tid);
        issue_tile(B, bn, K, p * CH_K, bb + 1 * TILE_B, tid);
        CP_COMMIT();
    }

    for (int c = 0; c < NCH; c++) {
        if (c + 1 < NCH) { CP_WAIT1(); } else { CP_WAIT0(); }
        __syncthreads();   // chunk c visible; slot (c+2)%3 free (read at c-1)

        if (c + 2 < NCH) {
            uint32_t nb = sb + (uint32_t)((c + 2) % 3) * STAGE_B;
            int kt = (c + 2) * CH_K;
            issue_tile(A, bm, K, kt, nb + 0 * TILE_B, tid);
            issue_tile(B, bn, K, kt, nb + 1 * TILE_B, tid);
            CP_COMMIT();
        }

        uint32_t bb  = sb + (uint32_t)(c % 3) * STAGE_B;
        uint32_t A_s = bb + 0 * TILE_B;
        uint32_t B_s = bb + 1 * TILE_B;

#pragma unroll
        for (int kk = 0; kk < 4; kk++) {
            uint32_t af[2][4];
#pragma unroll
            for (int i = 0; i < 2; i++) {
                uint32_t ro = (uint32_t)(m0 + i * 16 + a_row) * LDT_B
                              + kk * 32 + a_koff;
                LDSM_X4(af[i][0], af[i][1], af[i][2], af[i][3], A_s + ro);
            }
#pragma unroll
            for (int jp = 0; jp < 4; jp++) {
                uint32_t ro = (uint32_t)(n0 + jp * 16 + b_rin) * LDT_B
                              + kk * 32 + b_koff;
                uint32_t b0, b1, b2, b3;
                LDSM_X4(b0, b1, b2, b3, B_s + ro);
                mma_f16(acc[0][jp * 2 + 0], af[0], b0, b1);
                mma_f16(acc[0][jp * 2 + 1], af[0], b2, b3);
                mma_f16(acc[1][jp * 2 + 0], af[1], b0, b1);
                mma_f16(acc[1][jp * 2 + 1], af[1], b2, b3);
            }
        }
    }

    const int rrow = lane >> 2;
    const int rcol = (lane & 3) * 2;
#pragma unroll
    for (int i = 0; i < 2; i++) {
#pragma unroll
        for (int half = 0; half < 2; half++) {
            int row = bm + m0 + i * 16 + rrow + half * 8;
            if (MODE == 0) {
#pragma unroll
                for (int j = 0; j < 8; j++) {
                    int col = bn + n0 + j * 8 + rcol;
                    float b0 = bias[col], b1 = bias[col + 1];
                    *(float2*)&C[(size_t)row * N + col] =
                        make_float2(acc[i][j][half * 2 + 0] + b0,
                                    acc[i][j][half * 2 + 1] + b1);
                }
            } else {
                // n0 is 64-aligned, bn 128-aligned -> all 8 j's share one
                // head section; hoist sec/head/base out of the j loop.
                int colbase = bn + n0;
                int sec = colbase >> 10;           // 0=q 1=k 2=v
                int hh  = (colbase & 1023) >> 6;
                int b   = row >> 11, s = row & 2047;
                size_t dstb = (((size_t)(b * NH + hh)) * S_LEN + s) * HD
                              + (colbase & 63) + rcol;
                __half* p = (sec == 0) ? Q : (sec == 1) ? Kd : V;
                const float sc = (sec == 0) ? 0.125f * LOG2E : 1.0f;
#pragma unroll
                for (int j = 0; j < 8; j++) {
                    int col = colbase + j * 8 + rcol;
                    float v0 = (acc[i][j][half * 2 + 0] + bias[col]) * sc;
                    float v1 = (acc[i][j][half * 2 + 1] + bias[col + 1]) * sc;
                    *(uint32_t*)(p + dstb + j * 8) = pack_h2(v0, v1);
                }
            }
        }
    }
}

// ---------------------------------------------------------------------------
// Tensor-core flash attention (causal), all-f16 operands — R12 version.
// 64-key blocks, 3-stage cp.async; deferred-base softmax; exp+pack+PV fused
// per ks-stage so MUFU overlaps the tensor pipe.
// ---------------------------------------------------------------------------
#define ALD      144
#define KV_TILE  (64 * ALD)          // 9216 B
#define FA_STAGE (2 * KV_TILE)       // K, V = 18432 B
#define FA_SMEM  (3 * FA_STAGE)      // 55296 B

__global__ __launch_bounds__(256, 2) void flash_tc(
    const __half* __restrict__ Q,
    const __half* __restrict__ K,
    const __half* __restrict__ V,
    __half* __restrict__ Cc)
{
    extern __shared__ char sm[];
    uint32_t sb = smem_u32(sm);
    const int tid = threadIdx.x, lane = tid & 31, wid = tid >> 5;
    const int qb = (int)gridDim.x - 1 - (int)blockIdx.x;   // big tiles first
    const int h = blockIdx.y, b = blockIdx.z;
    const size_t hoff = ((size_t)(b * NH + h)) * S_LEN * HD;
    const __half* Q_g = Q + hoff + (size_t)qb * 128 * HD;
    const __half* K_g = K + hoff;
    const __half* V_g = V + hoff;

    // ---- stage Q (temporarily at sb), load fragments ----
#pragma unroll
    for (int i = 0; i < 4; i++) {
        int idx = tid + i * 256;
        int r = idx >> 3, c = idx & 7;
        CP_ASYNC16(sb + (uint32_t)(r * ALD + c * 16), Q_g + r * HD + c * 8);
    }
    CP_COMMIT(); CP_WAIT0(); __syncthreads();

    uint32_t qf[4][4];
    {
        uint32_t base = sb + (uint32_t)((wid * 16 + (lane & 15)) * ALD)
                        + ((lane >> 4) & 1) * 16;
#pragma unroll
        for (int ks = 0; ks < 4; ks++)
            LDSM_X4(qf[ks][0], qf[ks][1], qf[ks][2], qf[ks][3], base + ks * 32);
    }
    __syncthreads();

    float o[8][4];
#pragma unroll
    for (int j = 0; j < 8; j++)
#pragma unroll
        for (int q = 0; q < 4; q++) o[j][q] = 0.f;
    float m[2] = {-1e30f, -1e30f}, lpart[2] = {0.f, 0.f};

    const uint32_t b_rin  = ((lane >> 4) & 1) * 8 + (lane & 7);
    const uint32_t b_koff = ((lane >> 3) & 1) * 16;
    const uint32_t v_row  = (lane & 7) + ((lane >> 3) & 1) * 8;
    const uint32_t v_coff = ((lane >> 4) & 1) * 16;

    const int nIter = 2 * qb + 2;

    // prologue: stage key-blocks 0, 1 into slots 0, 1
#pragma unroll
    for (int p = 0; p < 2; p++) {
        if (p < nIter) {
            uint32_t nb = sb + (uint32_t)p * FA_STAGE;
            int kbase = p * 64 * HD;
#pragma unroll
            for (int i = 0; i < 2; i++) {
                int idx = tid + i * 256;
                int r = idx >> 3, c = idx & 7;
                uint32_t d = nb + (uint32_t)(r * ALD + c * 16);
                int go = kbase + r * HD + c * 8;
                CP_ASYNC16(d + 0 * KV_TILE, K_g + go);
                CP_ASYNC16(d + 1 * KV_TILE, V_g + go);
            }
            CP_COMMIT();
        }
    }

    for (int it = 0; it < nIter; it++) {
        if (it + 1 < nIter) { CP_WAIT1(); } else { CP_WAIT0(); }
        __syncthreads();

        if (it + 2 < nIter) {
            uint32_t nb = sb + (uint32_t)((it + 2) % 3) * FA_STAGE;
            int kbase = (it + 2) * 64 * HD;
#pragma unroll
            for (int i = 0; i < 2; i++) {
                int idx = tid + i * 256;
                int r = idx >> 3, c = idx & 7;
                uint32_t d = nb + (uint32_t)(r * ALD + c * 16);
                int go = kbase + r * HD + c * 8;
                CP_ASYNC16(d + 0 * KV_TILE, K_g + go);
                CP_ASYNC16(d + 1 * KV_TILE, V_g + go);
            }
            CP_COMMIT();
        }

        uint32_t bb = sb + (uint32_t)(it % 3) * FA_STAGE;

        // ---- S = Q K^T (single f16), interleaved accumulators ----
        float s[8][4];
#pragma unroll
        for (int j = 0; j < 8; j++)
#pragma unroll
            for (int q = 0; q < 4; q++) s[j][q] = 0.f;

#pragma unroll
        for (int ks = 0; ks < 4; ks++) {
#pragma unroll
            for (int jp = 0; jp < 4; jp++) {
                uint32_t ka = bb + (uint32_t)((jp * 16 + b_rin) * ALD)
                              + ks * 32 + b_koff;
                uint32_t k0, k1, k2, k3;
                LDSM_X4(k0, k1, k2, k3, ka);
                mma_f16(s[jp * 2 + 0], qf[ks], k0, k1);
                mma_f16(s[jp * 2 + 1], qf[ks], k2, k3);
            }
        }

        // ---- causal mask ----
        if (it >= 2 * qb) {
            int col0 = it * 64 + (lane & 3) * 2;
#pragma unroll
            for (int rr = 0; rr < 2; rr++) {
                int row = qb * 128 + wid * 16 + (lane >> 2) + rr * 8;
#pragma unroll
                for (int j = 0; j < 8; j++) {
                    int c0 = col0 + j * 8;
                    if (c0 > row)     s[j][rr * 2 + 0] = -1e30f;
                    if (c0 + 1 > row) s[j][rr * 2 + 1] = -1e30f;
                }
            }
        }

        // ---- deferred-base check + rare rescale (per row pair) ----
#pragma unroll
        for (int rr = 0; rr < 2; rr++) {
            float lmt = -1e30f;
#pragma unroll
            for (int j = 0; j < 8; j++)
                lmt = fmaxf(lmt, fmaxf(s[j][rr * 2], s[j][rr * 2 + 1]));
            if (__any_sync(0xffffffffu, lmt > m[rr] + 8.0f)) {  // rare
                float lm = fmaxf(lmt, __shfl_xor_sync(0xffffffffu, lmt, 1));
                lm = fmaxf(lm, __shfl_xor_sync(0xffffffffu, lm, 2));
                float mn = fmaxf(m[rr], lm);
                float corr = exp2f(m[rr] - mn);
                lpart[rr] *= corr;
#pragma unroll
                for (int j = 0; j < 8; j++) {
                    o[j][rr * 2 + 0] *= corr;
                    o[j][rr * 2 + 1] *= corr;
                }
                m[rr] = mn;
            }
        }
        const float mn0 = m[0], mn1 = m[1];

        // ---- fused exp + pack + PV per ks-stage (MUFU/tensor overlap) ----
        float sum0 = 0.f, sum1 = 0.f;
#pragma unroll
        for (int ks = 0; ks < 4; ks++) {
#pragma unroll
            for (int jj = 0; jj < 2; jj++) {
                int j = 2 * ks + jj;
                s[j][0] = exp2f(s[j][0] - mn0);
                s[j][1] = exp2f(s[j][1] - mn0);
                sum0 += s[j][0] + s[j][1];
                s[j][2] = exp2f(s[j][2] - mn1);
                s[j][3] = exp2f(s[j][3] - mn1);
                sum1 += s[j][2] + s[j][3];
            }
            uint32_t p16[4];
            p16[0] = pack_h2(s[2 * ks][0],     s[2 * ks][1]);
            p16[1] = pack_h2(s[2 * ks][2],     s[2 * ks][3]);
            p16[2] = pack_h2(s[2 * ks + 1][0], s[2 * ks + 1][1]);
            p16[3] = pack_h2(s[2 * ks + 1][2], s[2 * ks + 1][3]);
            uint32_t va = bb + KV_TILE
                          + (uint32_t)((ks * 16 + v_row) * ALD) + v_coff;
#pragma unroll
            for (int ng = 0; ng < 4; ng++) {
                uint32_t v0, v1, v2, v3;
                LDSM_X4_T(v0, v1, v2, v3, va + ng * 32);
                mma_f16(o[ng * 2 + 0], p16, v0, v1);
                mma_f16(o[ng * 2 + 1], p16, v2, v3);
            }
        }
        lpart[0] += sum0;
        lpart[1] += sum1;
    }

    // ---- epilogue: quad-reduce l, O/l -> ctx f16 [tok][H] ----
#pragma unroll
    for (int rr = 0; rr < 2; rr++) {
        float lsum = lpart[rr];
        lsum += __shfl_xor_sync(0xffffffffu, lsum, 1);
        lsum += __shfl_xor_sync(0xffffffffu, lsum, 2);
        float inv = 1.0f / lsum;
        int tok = b * S_LEN + qb * 128 + wid * 16 + (lane >> 2) + rr * 8;
#pragma unroll
        for (int j = 0; j < 8; j++) {
            int col = h * HD + j * 8 + (lane & 3) * 2;
            *(uint32_t*)(Cc + (size_t)tok * HID + col) =
                pack_h2(o[j][rr * 2 + 0] * inv, o[j][rr * 2 + 1] * inv);
        }
    }
}

// ---------------------------------------------------------------------------
extern "C" void kernel_launch(void* const* d_in, const int* in_sizes, int n_in,
                              void* d_out, int out_size)
{
    (void)in_sizes; (void)n_in; (void)out_size;
    const float* hidden  = (const float*)d_in[0];
    // d_in[1] = ltor_mask: exactly causal lower-triangular; handled analytically
    const float* W_qkv   = (const float*)d_in[2];
    const float* b_qkv   = (const float*)d_in[3];
    const float* W_dense = (const float*)d_in[4];
    const float* b_dense = (const float*)d_in[5];
    float* out = (float*)d_out;

    __half *a, *bw, *bw2, *qp, *kp, *vp;
    cudaGetSymbolAddress((void**)&a,   g_A);
    cudaGetSymbolAddress((void**)&bw,  g_B);
    cudaGetSymbolAddress((void**)&bw2, g_B2);
    cudaGetSymbolAddress((void**)&qp,  g_Q);
    cudaGetSymbolAddress((void**)&kp,  g_K);
    cudaGetSymbolAddress((void**)&vp,  g_V);

    cudaFuncSetAttribute(gemm_tc<0>,
                         cudaFuncAttributeMaxDynamicSharedMemorySize, GEMM_SMEM);
    cudaFuncSetAttribute(gemm_tc<1>,
                         cudaFuncAttributeMaxDynamicSharedMemorySize, GEMM_SMEM);
    cudaFuncSetAttribute(flash_tc,
                         cudaFuncAttributeMaxDynamicSharedMemorySize, FA_SMEM);

    // 1) fused prep: hidden->f16, W_qkv->g_B, W_dense->g_B2
    prep_all<<<NCVT + NTQ + NTD, 256>>>(hidden, a, W_qkv, bw, W_dense, bw2);

    // 2) QKV GEMM with fused per-head epilogue (Q scaled 0.125*log2e)
    {
        dim3 grid(3 * HID / 128, M_TOK / 128);
        gemm_tc<1><<<grid, 256, GEMM_SMEM>>>(a, bw, b_qkv, nullptr,
                                             qp, kp, vp, M_TOK, 3 * HID, HID);
    }
    // 3) flash attention -> ctx f16 (into g_A, dense-GEMM input)
    {
        dim3 grid(S_LEN / 128, NH, B_SZ);
        flash_tc<<<grid, 256, FA_SMEM>>>(qp, kp, vp, a);
    }
    // 4) dense GEMM -> out (fp32)
    {
        dim3 grid(HID / 128, M_TOK / 128);
        gemm_tc<0><<<grid, 256, GEMM_SMEM>>>(a, bw2, b_dense, out,
                                             nullptr, nullptr, nullptr,
                                             M_TOK, HID, HID);
    }
}